// round 9
// baseline (speedup 1.0000x reference)
#include <cuda_runtime.h>
#include <cuda_pipeline_primitives.h>
#include <cstdint>

// Divergence of (average(M) * gradient(mu)) with periodic boundaries.
// Shapes: (B=16, C=1, H=1024, W=1024) fp32.
// out[p] = sum_ax [ v_ax(p) - v_ax(p - e_ax) ],  v_ax(p) = 0.5*(M[p+e]+M[p])*(mu[p+e]-mu[p])
//
// Hybrid burst kernel. Block = 256 threads = one 1024-float row; each block
// does a 4-row strip (6 rows incl. vertical halo). Per thread, 12 global
// requests are issued back-to-back:
//   - mu: 6 rows via __pipeline_memcpy_async into smem (register-free)
//   - M : 6 float4 direct global->register loads
// M halos via warp shuffle + boundary-lane global scalar; mu halos via
// shuffle of the center LDS + single-lane smem wrap read.

#define H_DIM 1024
#define W_DIM 1024
#define N_IMG 16
#define RSTRIP 4
#define NROWS (RSTRIP + 2)

__global__ __launch_bounds__(256, 4) void div_grad_kernel(
    const float* __restrict__ M,
    const float* __restrict__ mu,
    float* __restrict__ out)
{
    __shared__ float sU[NROWS][W_DIM];     // 24 KB

    const int t     = threadIdx.x;         // 0..255 : float4 column
    const int lane  = t & 31;
    const int strip = blockIdx.x & 255;    // 256 strips of 4 rows per image
    const int img   = blockIdx.x >> 8;

    const int h0 = strip << 2;             // 0..1020
    const size_t base = (size_t)img << 20;
    const float* Mi = M  + base;
    const float* Ui = mu + base;
    const int wb = t << 2;

    // Row indices: 0 = h0-1 (wrap), 1..4 = h0..h0+3, 5 = h0+4 (wrap)
    int hrow[NROWS];
    hrow[0] = (h0 - 1) & (H_DIM - 1);
    #pragma unroll
    for (int i = 1; i < NROWS - 1; ++i) hrow[i] = h0 + i - 1;
    hrow[NROWS - 1] = (h0 + RSTRIP) & (H_DIM - 1);

    // ---- Front burst: 6 async copies (mu) + boundary scalars + 6 LDG.128 (M)
    #pragma unroll
    for (int i = 0; i < NROWS; ++i)
        __pipeline_memcpy_async(&sU[i][wb], Ui + ((size_t)hrow[i] << 10) + wb, 16);
    __pipeline_commit();

    // Boundary-lane M halo scalars (issued inside the burst window)
    const int wl = (wb - 1) & (W_DIM - 1);
    const int wr = (wb + 4) & (W_DIM - 1);
    float bM[RSTRIP];
    if (lane == 0) {
        #pragma unroll
        for (int r = 0; r < RSTRIP; ++r) bM[r] = Mi[((size_t)hrow[r + 1] << 10) + wl];
    } else if (lane == 31) {
        #pragma unroll
        for (int r = 0; r < RSTRIP; ++r) bM[r] = Mi[((size_t)hrow[r + 1] << 10) + wr];
    } else {
        #pragma unroll
        for (int r = 0; r < RSTRIP; ++r) bM[r] = 0.f;
    }

    float4 m[NROWS];
    #pragma unroll
    for (int i = 0; i < NROWS; ++i)
        m[i] = *reinterpret_cast<const float4*>(Mi + ((size_t)hrow[i] << 10) + wb);

    // M horizontal halos via shuffle
    const unsigned FULL = 0xffffffffu;
    float lM[RSTRIP], rM[RSTRIP];
    #pragma unroll
    for (int r = 0; r < RSTRIP; ++r) {
        lM[r] = __shfl_up_sync(FULL, m[r + 1].w, 1);
        rM[r] = __shfl_down_sync(FULL, m[r + 1].x, 1);
    }
    if (lane == 0) {
        #pragma unroll
        for (int r = 0; r < RSTRIP; ++r) lM[r] = bM[r];
    } else if (lane == 31) {
        #pragma unroll
        for (int r = 0; r < RSTRIP; ++r) rM[r] = bM[r];
    }

    __pipeline_wait_prior(0);
    __syncthreads();

    float* Oi = out + base;

    // Rolling mu window from smem
    float4 uup = *reinterpret_cast<const float4*>(&sU[0][wb]);
    float4 u   = *reinterpret_cast<const float4*>(&sU[1][wb]);

    #pragma unroll
    for (int r = 0; r < RSTRIP; ++r) {
        const int c = r + 1;
        const float4 udn = *reinterpret_cast<const float4*>(&sU[c + 1][wb]);

        // mu horizontal halos: shuffle of center regs; edge lanes read smem wrap
        float lU = __shfl_up_sync(FULL, u.w, 1);
        float rU = __shfl_down_sync(FULL, u.x, 1);
        if (lane == 0)       lU = sU[c][wl];
        else if (lane == 31) rU = sU[c][wr];

        const float4 mc  = m[c];
        const float4 mup = m[c - 1];
        const float4 mdn = m[c + 1];

        // W-direction forward fluxes (backward flux of elem e == forward of e-1)
        float vm = 0.5f * (mc.x + lM[r]) * (u.x - lU);
        float v0 = 0.5f * (mc.y + mc.x)  * (u.y - u.x);
        float v1 = 0.5f * (mc.z + mc.y)  * (u.z - u.y);
        float v2 = 0.5f * (mc.w + mc.z)  * (u.w - u.z);
        float v3 = 0.5f * (rM[r] + mc.w) * (rU  - u.w);

        float4 res;
        res.x = (v0 - vm) + 0.5f * (mdn.x + mc.x) * (udn.x - u.x) - 0.5f * (mc.x + mup.x) * (u.x - uup.x);
        res.y = (v1 - v0) + 0.5f * (mdn.y + mc.y) * (udn.y - u.y) - 0.5f * (mc.y + mup.y) * (u.y - uup.y);
        res.z = (v2 - v1) + 0.5f * (mdn.z + mc.z) * (udn.z - u.z) - 0.5f * (mc.z + mup.z) * (u.z - uup.z);
        res.w = (v3 - v2) + 0.5f * (mdn.w + mc.w) * (udn.w - u.w) - 0.5f * (mc.w + mup.w) * (u.w - uup.w);

        *reinterpret_cast<float4*>(Oi + ((size_t)(h0 + r) << 10) + wb) = res;

        uup = u;
        u   = udn;
    }
}

extern "C" void kernel_launch(void* const* d_in, const int* in_sizes, int n_in,
                              void* d_out, int out_size)
{
    const float* M  = (const float*)d_in[0];
    const float* mu = (const float*)d_in[1];
    float* out = (float*)d_out;

    const int grid = N_IMG * (H_DIM / RSTRIP);  // 4096 blocks
    div_grad_kernel<<<grid, 256>>>(M, mu, out);
}